// round 6
// baseline (speedup 1.0000x reference)
#include <cuda_runtime.h>
#include <cuda_bf16.h>
#include <cstdint>

#define DD 128
#define SMAX 4096
#define NMAX 1048576

// ---------------- scratch (device globals; no allocs allowed) ----------------
__device__ float          g_xs[SMAX * DD];          // segment sums (fp32)
__device__ float          g_xm[SMAX * DD];          // xs @ Lambda^T (fp32)
__device__ __nv_bfloat16  g_xbf[(size_t)NMAX * DD]; // bf16 copy of x (256 MB)
__device__ __nv_bfloat16  g_Gb[DD * DD];            // bf16 Gamma_W

__device__ __forceinline__ uint32_t smem_u32(const void* p) {
    uint32_t a;
    asm("{ .reg .u64 t; cvta.to.shared.u64 t, %1; cvt.u32.u64 %0, t; }"
        : "=r"(a) : "l"(p));
    return a;
}
__device__ __forceinline__ void cp_async16(uint32_t dst, const void* src) {
    asm volatile("cp.async.cg.shared.global [%0], [%1], 16;"
                 :: "r"(dst), "l"(src));
}
// 16B-unit swizzle: row-dependent XOR keeps ldmatrix 8-row reads conflict-free
#define SWZB(u, lr3) ((((((u) ^ (lr3)) & 7) | ((u) & 8))) << 4)

// ---------------- kernel 0: zero xs + convert Gamma_W -> bf16 ----------------
__global__ void prep_kernel(const float* __restrict__ GW) {
    int i = blockIdx.x * blockDim.x + threadIdx.x;
    if (i < SMAX * DD) g_xs[i] = 0.0f;
    if (i < DD * DD)   g_Gb[i] = __float2bfloat16(GW[i]);
}

// ---------------- kernel 1: segment sum + bf16 convert of x ----------------
// warp = 32 lanes x float4 = one 512B row; each warp owns SS_ROWS rows.
#define SS_ROWS 128
__global__ __launch_bounds__(256) void segsum_kernel(
    const float* __restrict__ x, const int* __restrict__ seg, int n)
{
    int lane = threadIdx.x & 31;
    int w = blockIdx.x * 8 + (threadIdx.x >> 5);
    int base = w * SS_ROWS;
    if (base >= n) return;
    int limit = n - base; if (limit > SS_ROWS) limit = SS_ROWS;

    float4 acc = make_float4(0.f, 0.f, 0.f, 0.f);
    int cur = -1;

    int r = 0;
    for (; r + 8 <= limit; r += 8) {
        int row = base + r;
        int ss[8]; float4 vv[8];
        #pragma unroll
        for (int j = 0; j < 8; j++) ss[j] = seg[row + j];
        #pragma unroll
        for (int j = 0; j < 8; j++)
            vv[j] = __ldcs((const float4*)(x + (size_t)(row + j) * DD + lane * 4));
        #pragma unroll
        for (int j = 0; j < 8; j++) {
            float4 v = vv[j]; int s = ss[j];
            if (s != cur) {
                if (cur >= 0) {
                    float* p = g_xs + (size_t)cur * DD + lane * 4;
                    atomicAdd(p + 0, acc.x); atomicAdd(p + 1, acc.y);
                    atomicAdd(p + 2, acc.z); atomicAdd(p + 3, acc.w);
                }
                acc = make_float4(0.f, 0.f, 0.f, 0.f);
                cur = s;
            }
            acc.x += v.x; acc.y += v.y; acc.z += v.z; acc.w += v.w;
            __nv_bfloat162 h0 = __float22bfloat162_rn(make_float2(v.x, v.y));
            __nv_bfloat162 h1 = __float22bfloat162_rn(make_float2(v.z, v.w));
            uint2 pk = make_uint2(reinterpret_cast<uint32_t&>(h0),
                                  reinterpret_cast<uint32_t&>(h1));
            __stcs((uint2*)(g_xbf + (size_t)(row + j) * DD + lane * 4), pk);
        }
    }
    for (; r < limit; r++) {
        int row = base + r;
        int s = seg[row];
        float4 v = __ldcs((const float4*)(x + (size_t)row * DD + lane * 4));
        if (s != cur) {
            if (cur >= 0) {
                float* p = g_xs + (size_t)cur * DD + lane * 4;
                atomicAdd(p + 0, acc.x); atomicAdd(p + 1, acc.y);
                atomicAdd(p + 2, acc.z); atomicAdd(p + 3, acc.w);
            }
            acc = make_float4(0.f, 0.f, 0.f, 0.f);
            cur = s;
        }
        acc.x += v.x; acc.y += v.y; acc.z += v.z; acc.w += v.w;
        __nv_bfloat162 h0 = __float22bfloat162_rn(make_float2(v.x, v.y));
        __nv_bfloat162 h1 = __float22bfloat162_rn(make_float2(v.z, v.w));
        uint2 pk = make_uint2(reinterpret_cast<uint32_t&>(h0),
                              reinterpret_cast<uint32_t&>(h1));
        __stcs((uint2*)(g_xbf + (size_t)row * DD + lane * 4), pk);
    }
    if (cur >= 0) {
        float* p = g_xs + (size_t)cur * DD + lane * 4;
        atomicAdd(p + 0, acc.x); atomicAdd(p + 1, acc.y);
        atomicAdd(p + 2, acc.z); atomicAdd(p + 3, acc.w);
    }
}

// ---------------- kernel 2: xm = xs @ Lambda^T (fp32, 32 segs/block) --------
__global__ __launch_bounds__(128) void xm_kernel(const float* __restrict__ LW) {
    __shared__ float xsh[32 * DD];
    int t = threadIdx.x;
    int s0 = blockIdx.x * 32;
    #pragma unroll
    for (int j = 0; j < 32; j++)
        xsh[j * DD + t] = g_xs[(size_t)(s0 + j) * DD + t];
    __syncthreads();
    float acc[32];
    #pragma unroll
    for (int j = 0; j < 32; j++) acc[j] = 0.0f;
    const float* lrow = LW + (size_t)t * DD;
    #pragma unroll 4
    for (int k = 0; k < DD; k++) {
        float lw = lrow[k];
        #pragma unroll
        for (int j = 0; j < 32; j++) acc[j] += xsh[j * DD + k] * lw;
    }
    #pragma unroll
    for (int j = 0; j < 32; j++)
        g_xm[(size_t)(s0 + j) * DD + t] = acc[j];
}

// ---------------- kernel 3: persistent HMMA GEMM, M=64 tiles, 3 CTAs/SM ----
// smem: As[0] 16KB | As[1] 16KB | Bs 32KB | bias 512B+pad  = 66 KB
#define TM 64
#define A_BYTES (TM * 256)               /* 16384 */
#define BIAS_SOFF (2 * A_BYTES + 32768)
#define GEMM_SMEM (BIAS_SOFF + 1024)

__device__ __forceinline__ void stage_A64(uint32_t dstbase, int t, int n, int tid) {
    int m0 = t * TM;
    #pragma unroll
    for (int i = 0; i < 4; i++) {
        int idx = tid + i * 256, row = idx >> 4, u = idx & 15;
        int gr = m0 + row; if (gr >= n) gr = n - 1;   // clamp; garbage never stored
        cp_async16(dstbase + row * 256 + SWZB(u, row & 7),
                   g_xbf + (size_t)gr * DD + u * 8);
    }
}

__global__ __launch_bounds__(256, 3) void gemm_kernel(
    const int* __restrict__ seg, const float* __restrict__ bias,
    float* __restrict__ out, int n, int ntiles)
{
    extern __shared__ char smraw[];
    uint32_t sb = smem_u32(smraw);
    uint32_t As[2] = { sb, sb + A_BYTES };
    uint32_t Bs = sb + 2 * A_BYTES;
    float* bsm = (float*)(smraw + BIAS_SOFF);

    int tid = threadIdx.x, lane = tid & 31, wid = tid >> 5;

    // bias -> smem; stage B (Gamma) once + first A tile
    if (tid < DD) bsm[tid] = bias[tid];
    #pragma unroll
    for (int i = 0; i < 8; i++) {
        int idx = tid + i * 256, row = idx >> 4, u = idx & 15;
        cp_async16(Bs + row * 256 + SWZB(u, row & 7), g_Gb + row * DD + u * 8);
    }
    stage_A64(As[0], blockIdx.x, n, tid);
    asm volatile("cp.async.commit_group;");

    // lane geometry: warp tile 16(M) x 64(N); warps 4(M) x 2(N)
    int wm = (wid & 3) * 16, wn = (wid >> 2) * 64;
    int g = lane >> 3, lr = lane & 7;
    int qr = lane >> 2, qc = 2 * (lane & 3);
    int a_m = (g & 1) * 8 + lr;
    int b_n = (g >> 1) * 8 + lr;
    int ua0 = g >> 1, ub0 = g & 1;

    uint32_t a_off = (uint32_t)((wm + a_m) * 256);
    uint32_t b_base[4];
    #pragma unroll
    for (int p = 0; p < 4; p++) b_base[p] = Bs + (uint32_t)((wn + b_n + p * 16) * 256);

    int buf = 0;
    for (int t = blockIdx.x; t < ntiles; t += gridDim.x, buf ^= 1) {
        asm volatile("cp.async.wait_group 0;" ::: "memory");
        __syncthreads();

        int tnext = t + gridDim.x;
        if (tnext < ntiles) {
            stage_A64(As[buf ^ 1], tnext, n, tid);
            asm volatile("cp.async.commit_group;");
        }

        int m0 = t * TM;
        bool full = (m0 + TM <= n);
        int sid[2];
        #pragma unroll
        for (int half = 0; half < 2; half++) {
            int m = m0 + wm + qr + half * 8;
            sid[half] = (full || m < n) ? seg[m] : 0;
        }

        float acc[8][4];
        #pragma unroll
        for (int b = 0; b < 8; b++)
            #pragma unroll
            for (int c = 0; c < 4; c++) acc[b][c] = 0.0f;

        uint32_t ab = As[buf] + a_off;
        #pragma unroll
        for (int kk = 0; kk < 8; kk++) {
            uint32_t asw = (uint32_t)SWZB(ua0 + 2 * kk, lr);
            uint32_t bsw = (uint32_t)SWZB(ub0 + 2 * kk, lr);
            uint32_t afrag[4];
            asm volatile("ldmatrix.sync.aligned.m8n8.x4.shared.b16 "
                         "{%0,%1,%2,%3}, [%4];"
                         : "=r"(afrag[0]), "=r"(afrag[1]),
                           "=r"(afrag[2]), "=r"(afrag[3])
                         : "r"(ab + asw));
            uint32_t bfrag[4][4];
            #pragma unroll
            for (int p = 0; p < 4; p++) {
                asm volatile("ldmatrix.sync.aligned.m8n8.x4.shared.b16 "
                             "{%0,%1,%2,%3}, [%4];"
                             : "=r"(bfrag[p][0]), "=r"(bfrag[p][1]),
                               "=r"(bfrag[p][2]), "=r"(bfrag[p][3])
                             : "r"(b_base[p] + bsw));
            }
            #pragma unroll
            for (int tn = 0; tn < 8; tn++) {
                uint32_t br0 = bfrag[tn >> 1][(tn & 1) * 2];
                uint32_t br1 = bfrag[tn >> 1][(tn & 1) * 2 + 1];
                asm volatile(
                    "mma.sync.aligned.m16n8k16.row.col.f32.bf16.bf16.f32 "
                    "{%0,%1,%2,%3}, {%4,%5,%6,%7}, {%8,%9}, {%0,%1,%2,%3};"
                    : "+f"(acc[tn][0]), "+f"(acc[tn][1]),
                      "+f"(acc[tn][2]), "+f"(acc[tn][3])
                    : "r"(afrag[0]), "r"(afrag[1]),
                      "r"(afrag[2]), "r"(afrag[3]),
                      "r"(br0), "r"(br1));
            }
        }

        // epilogue: + bias - xm[seg[m]], streaming float2 stores
        #pragma unroll
        for (int half = 0; half < 2; half++) {
            int m = m0 + wm + qr + half * 8;
            if (!full && m >= n) continue;
            const float* xmr = g_xm + (size_t)sid[half] * DD;
            float* orow = out + (size_t)m * DD;
            #pragma unroll
            for (int tn = 0; tn < 8; tn++) {
                int nc = wn + tn * 8 + qc;
                float2 xv = *(const float2*)(xmr + nc);
                float2 bv = *(const float2*)(bsm + nc);
                float2 rr;
                rr.x = acc[tn][half * 2 + 0] + bv.x - xv.x;
                rr.y = acc[tn][half * 2 + 1] + bv.y - xv.y;
                __stcs((float2*)(orow + nc), rr);
            }
        }
    }
}

// ---------------- launch ----------------
extern "C" void kernel_launch(void* const* d_in, const int* in_sizes, int n_in,
                              void* d_out, int out_size)
{
    const float* x   = (const float*)d_in[0];
    const int*   seg = (const int*)d_in[1];
    // d_in[2] = num_segments (statically 4096 here)
    const float* GW  = (const float*)d_in[3];
    const float* Gb  = (const float*)d_in[4];
    const float* LW  = (const float*)d_in[5];
    float* out = (float*)d_out;
    int n = in_sizes[0] / DD;
    int ntiles = (n + TM - 1) / TM;

    cudaFuncSetAttribute(gemm_kernel,
                         cudaFuncAttributeMaxDynamicSharedMemorySize, GEMM_SMEM);

    prep_kernel<<<(SMAX * DD + 255) / 256, 256>>>(GW);
    int nwarps = (n + SS_ROWS - 1) / SS_ROWS;
    segsum_kernel<<<(nwarps + 7) / 8, 256>>>(x, seg, n);
    xm_kernel<<<SMAX / 32, 128>>>(LW);
    int grid = 3 * 148; if (grid > ntiles) grid = ntiles;
    gemm_kernel<<<grid, 256, GEMM_SMEM>>>(seg, Gb, out, n, ntiles);
}

// round 9
// speedup vs baseline: 1.0542x; 1.0542x over previous
#include <cuda_runtime.h>
#include <cuda_bf16.h>
#include <cstdint>

#define DD 128
#define SMAX 4096
#define NMAX 1048576

// ---------------- scratch (device globals; no allocs allowed) ----------------
__device__ float          g_xs[SMAX * DD];          // segment sums (fp32)
__device__ float          g_xm[SMAX * DD];          // xs @ Lambda^T (fp32)
__device__ __nv_bfloat16  g_xbf[(size_t)NMAX * DD]; // bf16 copy of x (256 MB)
__device__ __nv_bfloat16  g_Gb[DD * DD];            // bf16 Gamma_W

__device__ __forceinline__ uint32_t smem_u32(const void* p) {
    uint32_t a;
    asm("{ .reg .u64 t; cvta.to.shared.u64 t, %1; cvt.u32.u64 %0, t; }"
        : "=r"(a) : "l"(p));
    return a;
}
__device__ __forceinline__ void cp_async16(uint32_t dst, const void* src) {
    asm volatile("cp.async.cg.shared.global [%0], [%1], 16;"
                 :: "r"(dst), "l"(src));
}
// 16B-unit swizzle: row-dependent XOR keeps ldmatrix 8-row reads conflict-free
#define SWZB(u, lr3) ((((((u) ^ (lr3)) & 7) | ((u) & 8))) << 4)

// ---------------- kernel 0: zero xs + convert Gamma_W -> bf16 ----------------
__global__ void prep_kernel(const float* __restrict__ GW) {
    int i = blockIdx.x * blockDim.x + threadIdx.x;
    if (i < SMAX * DD) g_xs[i] = 0.0f;
    if (i < DD * DD)   g_Gb[i] = __float2bfloat16(GW[i]);
}

// ---------------- kernel 1: segment sum + bf16 convert of x ----------------
#define SS_ROWS 128
__global__ __launch_bounds__(256) void segsum_kernel(
    const float* __restrict__ x, const int* __restrict__ seg, int n)
{
    int lane = threadIdx.x & 31;
    int w = blockIdx.x * 8 + (threadIdx.x >> 5);
    int base = w * SS_ROWS;
    if (base >= n) return;
    int limit = n - base; if (limit > SS_ROWS) limit = SS_ROWS;

    float4 acc = make_float4(0.f, 0.f, 0.f, 0.f);
    int cur = -1;

    int r = 0;
    for (; r + 8 <= limit; r += 8) {
        int row = base + r;
        int ss[8]; float4 vv[8];
        #pragma unroll
        for (int j = 0; j < 8; j++) ss[j] = seg[row + j];
        #pragma unroll
        for (int j = 0; j < 8; j++)
            vv[j] = __ldcs((const float4*)(x + (size_t)(row + j) * DD + lane * 4));
        #pragma unroll
        for (int j = 0; j < 8; j++) {
            float4 v = vv[j]; int s = ss[j];
            if (s != cur) {
                if (cur >= 0) {
                    float* p = g_xs + (size_t)cur * DD + lane * 4;
                    atomicAdd(p + 0, acc.x); atomicAdd(p + 1, acc.y);
                    atomicAdd(p + 2, acc.z); atomicAdd(p + 3, acc.w);
                }
                acc = make_float4(0.f, 0.f, 0.f, 0.f);
                cur = s;
            }
            acc.x += v.x; acc.y += v.y; acc.z += v.z; acc.w += v.w;
            __nv_bfloat162 h0 = __float22bfloat162_rn(make_float2(v.x, v.y));
            __nv_bfloat162 h1 = __float22bfloat162_rn(make_float2(v.z, v.w));
            uint2 pk = make_uint2(reinterpret_cast<uint32_t&>(h0),
                                  reinterpret_cast<uint32_t&>(h1));
            __stcs((uint2*)(g_xbf + (size_t)(row + j) * DD + lane * 4), pk);
        }
    }
    for (; r < limit; r++) {
        int row = base + r;
        int s = seg[row];
        float4 v = __ldcs((const float4*)(x + (size_t)row * DD + lane * 4));
        if (s != cur) {
            if (cur >= 0) {
                float* p = g_xs + (size_t)cur * DD + lane * 4;
                atomicAdd(p + 0, acc.x); atomicAdd(p + 1, acc.y);
                atomicAdd(p + 2, acc.z); atomicAdd(p + 3, acc.w);
            }
            acc = make_float4(0.f, 0.f, 0.f, 0.f);
            cur = s;
        }
        acc.x += v.x; acc.y += v.y; acc.z += v.z; acc.w += v.w;
        __nv_bfloat162 h0 = __float22bfloat162_rn(make_float2(v.x, v.y));
        __nv_bfloat162 h1 = __float22bfloat162_rn(make_float2(v.z, v.w));
        uint2 pk = make_uint2(reinterpret_cast<uint32_t&>(h0),
                              reinterpret_cast<uint32_t&>(h1));
        __stcs((uint2*)(g_xbf + (size_t)row * DD + lane * 4), pk);
    }
    if (cur >= 0) {
        float* p = g_xs + (size_t)cur * DD + lane * 4;
        atomicAdd(p + 0, acc.x); atomicAdd(p + 1, acc.y);
        atomicAdd(p + 2, acc.z); atomicAdd(p + 3, acc.w);
    }
}

// ---------------- kernel 2: xm = xs @ Lambda^T (fp32, 32 segs/block) --------
__global__ __launch_bounds__(128) void xm_kernel(const float* __restrict__ LW) {
    __shared__ float xsh[32 * DD];
    int t = threadIdx.x;
    int s0 = blockIdx.x * 32;
    #pragma unroll
    for (int j = 0; j < 32; j++)
        xsh[j * DD + t] = g_xs[(size_t)(s0 + j) * DD + t];
    __syncthreads();
    float acc[32];
    #pragma unroll
    for (int j = 0; j < 32; j++) acc[j] = 0.0f;
    const float* lrow = LW + (size_t)t * DD;
    #pragma unroll 4
    for (int k = 0; k < DD; k++) {
        float lw = lrow[k];
        #pragma unroll
        for (int j = 0; j < 32; j++) acc[j] += xsh[j * DD + k] * lw;
    }
    #pragma unroll
    for (int j = 0; j < 32; j++)
        g_xm[(size_t)(s0 + j) * DD + t] = acc[j];
}

// ------ kernel 3: persistent HMMA GEMM, B resident in regs, 3-stage A ------
// CTA tile 64(M) x 128(N); 8 warps as 2(M) x 4(N), warp tile 32x32.
// smem: A stages 3 x 16KB | Bs 32KB | bias  = 82 KB  (2 CTAs/SM)
#define TM 64
#define A_BYTES (TM * 256)               /* 16384 */
#define NSTAGE 3
#define BS_SOFF (NSTAGE * A_BYTES)
#define BIAS_SOFF (BS_SOFF + 32768)
#define GEMM_SMEM (BIAS_SOFF + 1024)

__device__ __forceinline__ void stage_A64(uint32_t dstbase, int t, int n, int tid) {
    int m0 = t * TM;
    #pragma unroll
    for (int i = 0; i < 4; i++) {
        int idx = tid + i * 256, row = idx >> 4, u = idx & 15;
        int gr = m0 + row; if (gr >= n) gr = n - 1;   // clamp; garbage never stored
        cp_async16(dstbase + row * 256 + SWZB(u, row & 7),
                   g_xbf + (size_t)gr * DD + u * 8);
    }
}

__global__ __launch_bounds__(256, 2) void gemm_kernel(
    const int* __restrict__ seg, const float* __restrict__ bias,
    float* __restrict__ out, int n, int ntiles)
{
    extern __shared__ char smraw[];
    uint32_t sb = smem_u32(smraw);
    uint32_t Bs = sb + BS_SOFF;
    float* bsm = (float*)(smraw + BIAS_SOFF);

    int tid = threadIdx.x, lane = tid & 31, wid = tid >> 5;

    // bias -> smem; stage B (Gamma) once
    if (tid < DD) bsm[tid] = bias[tid];
    #pragma unroll
    for (int i = 0; i < 8; i++) {
        int idx = tid + i * 256, row = idx >> 4, u = idx & 15;
        cp_async16(Bs + row * 256 + SWZB(u, row & 7), g_Gb + row * DD + u * 8);
    }
    asm volatile("cp.async.commit_group;");

    // prologue: stage first NSTAGE-1 A tiles, one group each
    #pragma unroll
    for (int s = 0; s < NSTAGE - 1; s++) {
        int t = blockIdx.x + s * gridDim.x;
        if (t < ntiles) stage_A64(sb + s * A_BYTES, t, n, tid);
        asm volatile("cp.async.commit_group;");
    }

    // lane geometry: warps 2(M) x 4(N); warp tile 32 x 32
    int wm = (wid & 1) * 32, wn = (wid >> 1) * 32;
    int g = lane >> 3, lr = lane & 7;
    int qr = lane >> 2, qc = 2 * (lane & 3);
    int a_m = (g & 1) * 8 + lr;
    int b_n = (g >> 1) * 8 + lr;
    int ua0 = g >> 1, ub0 = g & 1;

    // wait for B (oldest group) then pull all B fragments into registers
    asm volatile("cp.async.wait_group 2;" ::: "memory");
    __syncthreads();
    uint32_t barr[8][2][4];
    #pragma unroll
    for (int kk = 0; kk < 8; kk++) {
        uint32_t bsw = (uint32_t)SWZB(ub0 + 2 * kk, lr);
        #pragma unroll
        for (int p = 0; p < 2; p++) {
            uint32_t addr = Bs + (uint32_t)((wn + b_n + p * 16) * 256) + bsw;
            asm volatile("ldmatrix.sync.aligned.m8n8.x4.shared.b16 "
                         "{%0,%1,%2,%3}, [%4];"
                         : "=r"(barr[kk][p][0]), "=r"(barr[kk][p][1]),
                           "=r"(barr[kk][p][2]), "=r"(barr[kk][p][3])
                         : "r"(addr));
        }
    }

    uint32_t a_row_off = (uint32_t)((wm + a_m) * 256);

    int buf = 0;
    for (int t = blockIdx.x; t < ntiles; t += gridDim.x) {
        // oldest pending group = this tile's A stage
        asm volatile("cp.async.wait_group 1;" ::: "memory");
        __syncthreads();

        int tnext = t + (NSTAGE - 1) * gridDim.x;
        int nbuf = buf + (NSTAGE - 1); if (nbuf >= NSTAGE) nbuf -= NSTAGE;
        if (tnext < ntiles) stage_A64(sb + nbuf * A_BYTES, tnext, n, tid);
        asm volatile("cp.async.commit_group;");

        int m0 = t * TM;
        bool full = (m0 + TM <= n);
        int sid[2][2];
        #pragma unroll
        for (int tm = 0; tm < 2; tm++)
            #pragma unroll
            for (int half = 0; half < 2; half++) {
                int m = m0 + wm + tm * 16 + qr + half * 8;
                sid[tm][half] = (full || m < n) ? seg[m] : 0;
            }

        float acc[2][4][4];
        #pragma unroll
        for (int a = 0; a < 2; a++)
            #pragma unroll
            for (int b = 0; b < 4; b++)
                #pragma unroll
                for (int c = 0; c < 4; c++) acc[a][b][c] = 0.0f;

        uint32_t ab = sb + buf * A_BYTES + a_row_off;
        #pragma unroll
        for (int kk = 0; kk < 8; kk++) {
            uint32_t asw = (uint32_t)SWZB(ua0 + 2 * kk, lr);
            uint32_t afrag[2][4];
            #pragma unroll
            for (int tm = 0; tm < 2; tm++) {
                asm volatile("ldmatrix.sync.aligned.m8n8.x4.shared.b16 "
                             "{%0,%1,%2,%3}, [%4];"
                             : "=r"(afrag[tm][0]), "=r"(afrag[tm][1]),
                               "=r"(afrag[tm][2]), "=r"(afrag[tm][3])
                             : "r"(ab + tm * (16 * 256) + asw));
            }
            #pragma unroll
            for (int tm = 0; tm < 2; tm++) {
                #pragma unroll
                for (int tn = 0; tn < 4; tn++) {
                    uint32_t br0 = barr[kk][tn >> 1][(tn & 1) * 2];
                    uint32_t br1 = barr[kk][tn >> 1][(tn & 1) * 2 + 1];
                    asm volatile(
                        "mma.sync.aligned.m16n8k16.row.col.f32.bf16.bf16.f32 "
                        "{%0,%1,%2,%3}, {%4,%5,%6,%7}, {%8,%9}, {%0,%1,%2,%3};"
                        : "+f"(acc[tm][tn][0]), "+f"(acc[tm][tn][1]),
                          "+f"(acc[tm][tn][2]), "+f"(acc[tm][tn][3])
                        : "r"(afrag[tm][0]), "r"(afrag[tm][1]),
                          "r"(afrag[tm][2]), "r"(afrag[tm][3]),
                        "r"(br0), "r"(br1));
                }
            }
        }

        // epilogue: + bias - xm[seg[m]], streaming float2 stores
        #pragma unroll
        for (int tm = 0; tm < 2; tm++) {
            #pragma unroll
            for (int half = 0; half < 2; half++) {
                int m = m0 + wm + tm * 16 + qr + half * 8;
                if (!full && m >= n) continue;
                const float* xmr = g_xm + (size_t)sid[tm][half] * DD;
                float* orow = out + (size_t)m * DD;
                #pragma unroll
                for (int tn = 0; tn < 4; tn++) {
                    int nc = wn + tn * 8 + qc;
                    float2 xv = *(const float2*)(xmr + nc);
                    float2 bv = *(const float2*)(bsm + nc);
                    float2 rr;
                    rr.x = acc[tm][tn][half * 2 + 0] + bv.x - xv.x;
                    rr.y = acc[tm][tn][half * 2 + 1] + bv.y - xv.y;
                    __stcs((float2*)(orow + nc), rr);
                }
            }
        }
        buf++; if (buf >= NSTAGE) buf = 0;
    }
}

// ---------------- launch ----------------
extern "C" void kernel_launch(void* const* d_in, const int* in_sizes, int n_in,
                              void* d_out, int out_size)
{
    const float* x   = (const float*)d_in[0];
    const int*   seg = (const int*)d_in[1];
    // d_in[2] = num_segments (statically 4096 here)
    const float* GW  = (const float*)d_in[3];
    const float* Gb  = (const float*)d_in[4];
    const float* LW  = (const float*)d_in[5];
    float* out = (float*)d_out;
    int n = in_sizes[0] / DD;
    int ntiles = (n + TM - 1) / TM;

    cudaFuncSetAttribute(gemm_kernel,
                         cudaFuncAttributeMaxDynamicSharedMemorySize, GEMM_SMEM);

    prep_kernel<<<(SMAX * DD + 255) / 256, 256>>>(GW);
    int nwarps = (n + SS_ROWS - 1) / SS_ROWS;
    segsum_kernel<<<(nwarps + 7) / 8, 256>>>(x, seg, n);
    xm_kernel<<<SMAX / 32, 128>>>(LW);
    int grid = 2 * 148; if (grid > ntiles) grid = ntiles;
    gemm_kernel<<<grid, 256, GEMM_SMEM>>>(seg, Gb, out, n, ntiles);
}

// round 10
// speedup vs baseline: 1.1048x; 1.0480x over previous
#include <cuda_runtime.h>
#include <cuda_bf16.h>
#include <cstdint>

#define DD 128
#define SMAX 4096
#define NMAX 1048576

// ---------------- scratch (device globals; no allocs allowed) ----------------
__device__ float          g_xs[SMAX * DD];          // segment sums (fp32)
__device__ float          g_xm[SMAX * DD];          // xs @ Lambda^T (fp32)
__device__ __nv_bfloat16  g_xbf[(size_t)NMAX * DD]; // bf16 copy of x (256 MB)
__device__ __nv_bfloat16  g_Gb[DD * DD];            // bf16 Gamma_W

__device__ __forceinline__ uint32_t smem_u32(const void* p) {
    uint32_t a;
    asm("{ .reg .u64 t; cvta.to.shared.u64 t, %1; cvt.u32.u64 %0, t; }"
        : "=r"(a) : "l"(p));
    return a;
}
__device__ __forceinline__ void cp_async16(uint32_t dst, const void* src) {
    asm volatile("cp.async.cg.shared.global [%0], [%1], 16;"
                 :: "r"(dst), "l"(src));
}
// 16B-unit swizzle: row-dependent XOR keeps ldmatrix 8-row reads conflict-free
#define SWZB(u, lr3) ((((((u) ^ (lr3)) & 7) | ((u) & 8))) << 4)

// ---------------- kernel 0: zero xs + convert Gamma_W -> bf16 ----------------
__global__ void prep_kernel(const float* __restrict__ GW) {
    int i = blockIdx.x * blockDim.x + threadIdx.x;
    if (i < SMAX * DD) g_xs[i] = 0.0f;
    if (i < DD * DD)   g_Gb[i] = __float2bfloat16(GW[i]);
}

// ---------------- kernel 1: segment sum + bf16 convert of x ----------------
#define SS_ROWS 128
__global__ __launch_bounds__(256) void segsum_kernel(
    const float* __restrict__ x, const int* __restrict__ seg, int n)
{
    int lane = threadIdx.x & 31;
    int w = blockIdx.x * 8 + (threadIdx.x >> 5);
    int base = w * SS_ROWS;
    if (base >= n) return;
    int limit = n - base; if (limit > SS_ROWS) limit = SS_ROWS;

    float4 acc = make_float4(0.f, 0.f, 0.f, 0.f);
    int cur = -1;

    int r = 0;
    for (; r + 8 <= limit; r += 8) {
        int row = base + r;
        int ss[8]; float4 vv[8];
        #pragma unroll
        for (int j = 0; j < 8; j++) ss[j] = seg[row + j];
        #pragma unroll
        for (int j = 0; j < 8; j++)
            vv[j] = __ldcs((const float4*)(x + (size_t)(row + j) * DD + lane * 4));
        #pragma unroll
        for (int j = 0; j < 8; j++) {
            float4 v = vv[j]; int s = ss[j];
            if (s != cur) {
                if (cur >= 0) {
                    float* p = g_xs + (size_t)cur * DD + lane * 4;
                    atomicAdd(p + 0, acc.x); atomicAdd(p + 1, acc.y);
                    atomicAdd(p + 2, acc.z); atomicAdd(p + 3, acc.w);
                }
                acc = make_float4(0.f, 0.f, 0.f, 0.f);
                cur = s;
            }
            acc.x += v.x; acc.y += v.y; acc.z += v.z; acc.w += v.w;
            __nv_bfloat162 h0 = __float22bfloat162_rn(make_float2(v.x, v.y));
            __nv_bfloat162 h1 = __float22bfloat162_rn(make_float2(v.z, v.w));
            uint2 pk = make_uint2(reinterpret_cast<uint32_t&>(h0),
                                  reinterpret_cast<uint32_t&>(h1));
            __stcs((uint2*)(g_xbf + (size_t)(row + j) * DD + lane * 4), pk);
        }
    }
    for (; r < limit; r++) {
        int row = base + r;
        int s = seg[row];
        float4 v = __ldcs((const float4*)(x + (size_t)row * DD + lane * 4));
        if (s != cur) {
            if (cur >= 0) {
                float* p = g_xs + (size_t)cur * DD + lane * 4;
                atomicAdd(p + 0, acc.x); atomicAdd(p + 1, acc.y);
                atomicAdd(p + 2, acc.z); atomicAdd(p + 3, acc.w);
            }
            acc = make_float4(0.f, 0.f, 0.f, 0.f);
            cur = s;
        }
        acc.x += v.x; acc.y += v.y; acc.z += v.z; acc.w += v.w;
        __nv_bfloat162 h0 = __float22bfloat162_rn(make_float2(v.x, v.y));
        __nv_bfloat162 h1 = __float22bfloat162_rn(make_float2(v.z, v.w));
        uint2 pk = make_uint2(reinterpret_cast<uint32_t&>(h0),
                              reinterpret_cast<uint32_t&>(h1));
        __stcs((uint2*)(g_xbf + (size_t)row * DD + lane * 4), pk);
    }
    if (cur >= 0) {
        float* p = g_xs + (size_t)cur * DD + lane * 4;
        atomicAdd(p + 0, acc.x); atomicAdd(p + 1, acc.y);
        atomicAdd(p + 2, acc.z); atomicAdd(p + 3, acc.w);
    }
}

// ---------------- kernel 2: xm = xs @ Lambda^T (fp32, 16 segs/block) --------
__global__ __launch_bounds__(128) void xm_kernel(const float* __restrict__ LW) {
    __shared__ float xsh[16 * DD];
    int t = threadIdx.x;
    int s0 = blockIdx.x * 16;
    #pragma unroll
    for (int j = 0; j < 16; j++)
        xsh[j * DD + t] = g_xs[(size_t)(s0 + j) * DD + t];
    __syncthreads();
    float acc[16];
    #pragma unroll
    for (int j = 0; j < 16; j++) acc[j] = 0.0f;
    const float* lrow = LW + (size_t)t * DD;
    #pragma unroll 4
    for (int k = 0; k < DD; k++) {
        float lw = lrow[k];
        #pragma unroll
        for (int j = 0; j < 16; j++) acc[j] += xsh[j * DD + k] * lw;
    }
    #pragma unroll
    for (int j = 0; j < 16; j++)
        g_xm[(size_t)(s0 + j) * DD + t] = acc[j];
}

// ---- kernel 3: persistent HMMA GEMM (R4 geometry) + batched-load epilogue --
// CTA tile 128x128; 8 warps as 4(M) x 2(N), warp tile 32x64.
// smem: As[0] 32KB | As[1] 32KB | Bs 32KB | bias = 96.5 KB (2 CTAs/SM)
#define A_BYTES 32768
#define BIAS_SOFF (3 * A_BYTES)
#define GEMM_SMEM (BIAS_SOFF + 1024)

__device__ __forceinline__ void stage_A128(uint32_t dstbase, int t, int n, int tid) {
    int m0 = t * 128;
    #pragma unroll
    for (int i = 0; i < 8; i++) {
        int idx = tid + i * 256, row = idx >> 4, u = idx & 15;
        int gr = m0 + row; if (gr >= n) gr = n - 1;   // clamp; garbage never stored
        cp_async16(dstbase + row * 256 + SWZB(u, row & 7),
                   g_xbf + (size_t)gr * DD + u * 8);
    }
}

__global__ __launch_bounds__(256, 2) void gemm_kernel(
    const int* __restrict__ seg, const float* __restrict__ bias,
    float* __restrict__ out, int n, int ntiles)
{
    extern __shared__ char smraw[];
    uint32_t sb = smem_u32(smraw);
    uint32_t As[2] = { sb, sb + A_BYTES };
    uint32_t Bs = sb + 2 * A_BYTES;
    float* bsm = (float*)(smraw + BIAS_SOFF);

    int tid = threadIdx.x, lane = tid & 31, wid = tid >> 5;

    // bias -> smem; stage B (Gamma) once + first A tile, one group
    if (tid < DD) bsm[tid] = bias[tid];
    #pragma unroll
    for (int i = 0; i < 8; i++) {
        int idx = tid + i * 256, row = idx >> 4, u = idx & 15;
        cp_async16(Bs + row * 256 + SWZB(u, row & 7), g_Gb + row * DD + u * 8);
    }
    stage_A128(As[0], blockIdx.x, n, tid);
    asm volatile("cp.async.commit_group;");

    // lane geometry: warps 4(M) x 2(N); warp tile 32 x 64
    int wm = (wid & 3) * 32, wn = (wid >> 2) * 64;
    int g = lane >> 3, lr = lane & 7;
    int qr = lane >> 2, qc = 2 * (lane & 3);
    int a_m = (g & 1) * 8 + lr;
    int b_n = (g >> 1) * 8 + lr;
    int ua0 = g >> 1, ub0 = g & 1;

    uint32_t a_off[2], b_base[4];
    #pragma unroll
    for (int tm = 0; tm < 2; tm++) a_off[tm] = (uint32_t)((wm + a_m + tm * 16) * 256);
    #pragma unroll
    for (int p = 0; p < 4; p++) b_base[p] = Bs + (uint32_t)((wn + b_n + p * 16) * 256);

    int buf = 0;
    for (int t = blockIdx.x; t < ntiles; t += gridDim.x, buf ^= 1) {
        asm volatile("cp.async.wait_group 0;" ::: "memory");
        __syncthreads();

        int tnext = t + gridDim.x;
        if (tnext < ntiles) {
            stage_A128(As[buf ^ 1], tnext, n, tid);
            asm volatile("cp.async.commit_group;");
        }

        int m0 = t * 128;
        bool full = (m0 + 128 <= n);
        int sid[2][2];
        #pragma unroll
        for (int tm = 0; tm < 2; tm++)
            #pragma unroll
            for (int half = 0; half < 2; half++) {
                int m = m0 + wm + tm * 16 + qr + half * 8;
                sid[tm][half] = (full || m < n) ? seg[m] : 0;
            }

        float acc[2][8][4];
        #pragma unroll
        for (int a = 0; a < 2; a++)
            #pragma unroll
            for (int b = 0; b < 8; b++)
                #pragma unroll
                for (int c = 0; c < 4; c++) acc[a][b][c] = 0.0f;

        uint32_t ab = As[buf];
        #pragma unroll
        for (int kk = 0; kk < 8; kk++) {
            uint32_t asw = (uint32_t)SWZB(ua0 + 2 * kk, lr);
            uint32_t bsw = (uint32_t)SWZB(ub0 + 2 * kk, lr);
            uint32_t afrag[2][4];
            #pragma unroll
            for (int tm = 0; tm < 2; tm++) {
                asm volatile("ldmatrix.sync.aligned.m8n8.x4.shared.b16 "
                             "{%0,%1,%2,%3}, [%4];"
                             : "=r"(afrag[tm][0]), "=r"(afrag[tm][1]),
                               "=r"(afrag[tm][2]), "=r"(afrag[tm][3])
                             : "r"(ab + a_off[tm] + asw));
            }
            uint32_t bfrag[4][4];
            #pragma unroll
            for (int p = 0; p < 4; p++) {
                asm volatile("ldmatrix.sync.aligned.m8n8.x4.shared.b16 "
                             "{%0,%1,%2,%3}, [%4];"
                             : "=r"(bfrag[p][0]), "=r"(bfrag[p][1]),
                               "=r"(bfrag[p][2]), "=r"(bfrag[p][3])
                             : "r"(b_base[p] + bsw));
            }
            #pragma unroll
            for (int tm = 0; tm < 2; tm++) {
                #pragma unroll
                for (int tn = 0; tn < 8; tn++) {
                    uint32_t br0 = bfrag[tn >> 1][(tn & 1) * 2];
                    uint32_t br1 = bfrag[tn >> 1][(tn & 1) * 2 + 1];
                    asm volatile(
                        "mma.sync.aligned.m16n8k16.row.col.f32.bf16.bf16.f32 "
                        "{%0,%1,%2,%3}, {%4,%5,%6,%7}, {%8,%9}, {%0,%1,%2,%3};"
                        : "+f"(acc[tm][tn][0]), "+f"(acc[tm][tn][1]),
                          "+f"(acc[tm][tn][2]), "+f"(acc[tm][tn][3])
                        : "r"(afrag[tm][0]), "r"(afrag[tm][1]),
                          "r"(afrag[tm][2]), "r"(afrag[tm][3]),
                          "r"(br0), "r"(br1));
                }
            }
        }

        // epilogue: batch ALL xm loads of a group into regs BEFORE any store,
        // so no store-order hazard serializes the L2 loads.
        #pragma unroll
        for (int tm = 0; tm < 2; tm++) {
            #pragma unroll
            for (int half = 0; half < 2; half++) {
                int m = m0 + wm + tm * 16 + qr + half * 8;
                if (!full && m >= n) continue;
                const float* __restrict__ xmr = g_xm + (size_t)sid[tm][half] * DD;
                float2 xv[8];
                #pragma unroll
                for (int tn = 0; tn < 8; tn++)
                    xv[tn] = *(const float2*)(xmr + wn + tn * 8 + qc);
                float* __restrict__ orow = out + (size_t)m * DD;
                #pragma unroll
                for (int tn = 0; tn < 8; tn++) {
                    int nc = wn + tn * 8 + qc;
                    float2 bv = *(const float2*)(bsm + nc);
                    float2 rr;
                    rr.x = acc[tm][tn][half * 2 + 0] + bv.x - xv[tn].x;
                    rr.y = acc[tm][tn][half * 2 + 1] + bv.y - xv[tn].y;
                    *(float2*)(orow + nc) = rr;
                }
            }
        }
    }
}

// ---------------- launch ----------------
extern "C" void kernel_launch(void* const* d_in, const int* in_sizes, int n_in,
                              void* d_out, int out_size)
{
    const float* x   = (const float*)d_in[0];
    const int*   seg = (const int*)d_in[1];
    // d_in[2] = num_segments (statically 4096 here)
    const float* GW  = (const float*)d_in[3];
    const float* Gb  = (const float*)d_in[4];
    const float* LW  = (const float*)d_in[5];
    float* out = (float*)d_out;
    int n = in_sizes[0] / DD;
    int ntiles = (n + 127) / 128;

    cudaFuncSetAttribute(gemm_kernel,
                         cudaFuncAttributeMaxDynamicSharedMemorySize, GEMM_SMEM);

    prep_kernel<<<(SMAX * DD + 255) / 256, 256>>>(GW);
    int nwarps = (n + SS_ROWS - 1) / SS_ROWS;
    segsum_kernel<<<(nwarps + 7) / 8, 256>>>(x, seg, n);
    xm_kernel<<<SMAX / 16, 128>>>(LW);
    int grid = 296; if (grid > ntiles) grid = ntiles;
    gemm_kernel<<<grid, 256, GEMM_SMEM>>>(seg, Gb, out, n, ntiles);
}